// round 1
// baseline (speedup 1.0000x reference)
#include <cuda_runtime.h>
#include <math.h>

// Problem constants
#define NB    4          // batch
#define NN    1000       // nodes per graph
#define NT    8          // timesteps
#define NF    64         // in features
#define NH    64         // hidden
#define NHEAD 4
#define NE    16000      // edges per graph
#define NG    32         // NB*NT graphs
#define GN    32000      // NG*NN total nodes
#define BN    4000       // NB*NN gru rows
#define TOTE  512000     // NG*NE total edges
#define NEG_SLOPE 0.2f

// -------------------- scratch (device globals, no runtime alloc) ------------
__device__ float g_hfeat[GN * 256];     // per-layer h = in @ W   [node, head*64+ch]
__device__ float g_asrc[GN * 4];
__device__ float g_adst[GN * 4];
__device__ float g_gat1[GN * 64];       // layer1 output (relu'd)
__device__ float g_gat2[GN * 64];       // layer2 output
__device__ float g_gi[NT * BN * 192];   // precomputed xs @ Wih0^T + bih0
__device__ float g_h1[BN * 64];
__device__ float g_h2[BN * 64];
__device__ int   g_deg[GN];
__device__ int   g_offs[GN + 1];
__device__ int   g_cursor[GN];
__device__ int   g_srclist[TOTE];       // local src node ids, sorted by dst

// -------------------- init: zero deg + GRU states ---------------------------
__global__ void init_kernel() {
    int total = GN + BN * 64 * 2;
    for (int i = blockIdx.x * blockDim.x + threadIdx.x; i < total;
         i += gridDim.x * blockDim.x) {
        if (i < GN) g_deg[i] = 0;
        else if (i < GN + BN * 64) g_h1[i - GN] = 0.f;
        else g_h2[i - GN - BN * 64] = 0.f;
    }
}

// -------------------- CSR build ----------------------------------------------
__global__ void hist_kernel(const int* __restrict__ ei) {
    for (int e = blockIdx.x * blockDim.x + threadIdx.x; e < TOTE;
         e += gridDim.x * blockDim.x) {
        int g = e / NE, el = e % NE;
        int dst = ei[(g * 2 + 1) * NE + el];
        atomicAdd(&g_deg[g * NN + dst], 1);
    }
}

__global__ void scan_kernel() {
    __shared__ int wsum[32];
    int tid = threadIdx.x, lane = tid & 31, wid = tid >> 5;
    int base = tid * 32;
    int local = 0;
    for (int i = 0; i < 32; i++) {
        int idx = base + i;
        if (idx < GN) local += g_deg[idx];
    }
    int s = local;
    for (int d = 1; d < 32; d <<= 1) {
        int v = __shfl_up_sync(0xffffffffu, s, d);
        if (lane >= d) s += v;
    }
    if (lane == 31) wsum[wid] = s;
    __syncthreads();
    if (wid == 0) {
        int v = wsum[lane];
        for (int d = 1; d < 32; d <<= 1) {
            int u = __shfl_up_sync(0xffffffffu, v, d);
            if (lane >= d) v += u;
        }
        wsum[lane] = v;  // inclusive scan of warp sums
    }
    __syncthreads();
    int prefix = s - local + (wid > 0 ? wsum[wid - 1] : 0);
    int run = prefix;
    for (int i = 0; i < 32; i++) {
        int idx = base + i;
        if (idx < GN) {
            g_offs[idx] = run;
            g_cursor[idx] = run;
            run += g_deg[idx];
        }
    }
    if (tid == 1023) g_offs[GN] = run;
}

__global__ void scatter_kernel(const int* __restrict__ ei) {
    for (int e = blockIdx.x * blockDim.x + threadIdx.x; e < TOTE;
         e += gridDim.x * blockDim.x) {
        int g = e / NE, el = e % NE;
        int src = ei[(g * 2 + 0) * NE + el];
        int dst = ei[(g * 2 + 1) * NE + el];
        int pos = atomicAdd(&g_cursor[g * NN + dst], 1);
        g_srclist[pos] = src;
    }
}

// -------------------- GAT prologue: hfeat = in @ W (64 -> 256) --------------
// block: 256 threads, 64 nodes per block. thread owns one output channel.
__global__ __launch_bounds__(256)
void prologue_kernel(const float* __restrict__ in, const float* __restrict__ W,
                     int mode) {
    __shared__ float xs[4096];
    int tid = threadIdx.x;
    int nodebase = blockIdx.x * 64;
    for (int i = tid; i < 4096; i += 256) {
        int r = i >> 6, k = i & 63;
        int node = nodebase + r;
        float v;
        if (mode == 0) {
            int gg = node / NN, n = node % NN;
            int b = gg >> 3, t = gg & 7;
            v = in[((b * NN + n) * NT + t) * NF + k];
        } else {
            v = g_gat1[node * 64 + k];
        }
        xs[i] = v;
    }
    __syncthreads();
    float acc[64];
#pragma unroll
    for (int r = 0; r < 64; r++) acc[r] = 0.f;
    for (int k = 0; k < 64; k++) {
        float w = W[k * 256 + tid];
#pragma unroll
        for (int r = 0; r < 64; r++) acc[r] += xs[r * 64 + k] * w;
    }
    for (int r = 0; r < 64; r++)
        g_hfeat[(nodebase + r) * 256 + tid] = acc[r];
}

// -------------------- attention scalar reductions ---------------------------
__global__ void att_kernel(const float* __restrict__ att_src,
                           const float* __restrict__ att_dst) {
    __shared__ float sa[256], sd[256];
    int node = blockIdx.x;
    int tid = threadIdx.x;
    float h = g_hfeat[node * 256 + tid];
    sa[tid] = h * att_src[tid];
    sd[tid] = h * att_dst[tid];
    __syncthreads();
    for (int s = 32; s > 0; s >>= 1) {
        if ((tid & 63) < s) {
            sa[tid] += sa[tid + s];
            sd[tid] += sd[tid + s];
        }
        __syncthreads();
    }
    if ((tid & 63) == 0) {
        int hd = tid >> 6;
        g_asrc[node * 4 + hd] = sa[tid];
        g_adst[node * 4 + hd] = sd[tid];
    }
}

// -------------------- GAT aggregation (softmax + weighted sum) --------------
__device__ __forceinline__ float leaky(float e) {
    return e > 0.f ? e : NEG_SLOPE * e;
}

__global__ __launch_bounds__(256)
void aggregate_kernel(const float* __restrict__ bias, int relu_flag, int which) {
    __shared__ float sm_m[4], sm_s[4];
    __shared__ float sm_alpha[128 * 4];
    __shared__ int   sm_src[128];
    __shared__ float sred[256];

    int node = blockIdx.x;
    int g = node / NN;
    int tid = threadIdx.x;
    int off = g_offs[node];
    int deg = g_offs[node + 1] - off;

    if (tid < 128) {
        int hd = tid >> 5, lane = tid & 31;
        float adst_h = g_adst[node * 4 + hd];
        float e_self = leaky(g_asrc[node * 4 + hd] + adst_h);
        float m = e_self;
        for (int j = lane; j < deg; j += 32) {
            int srcg = g * NN + g_srclist[off + j];
            m = fmaxf(m, leaky(g_asrc[srcg * 4 + hd] + adst_h));
        }
        for (int d = 16; d; d >>= 1)
            m = fmaxf(m, __shfl_xor_sync(0xffffffffu, m, d));
        float s = (lane == 0) ? expf(e_self - m) : 0.f;
        for (int j = lane; j < deg; j += 32) {
            int srcg = g * NN + g_srclist[off + j];
            s += expf(leaky(g_asrc[srcg * 4 + hd] + adst_h) - m);
        }
        for (int d = 16; d; d >>= 1)
            s += __shfl_xor_sync(0xffffffffu, s, d);
        if (lane == 0) { sm_m[hd] = m; sm_s[hd] = s; }
    }
    __syncthreads();

    int hd = tid >> 6;
    float m = sm_m[hd];
    float sinv = 1.f / sm_s[hd];
    float e_self = leaky(g_asrc[node * 4 + hd] + g_adst[node * 4 + hd]);
    float acc = expf(e_self - m) * sinv * g_hfeat[node * 256 + tid];

    for (int base = 0; base < deg; base += 128) {
        int cnt = min(128, deg - base);
        __syncthreads();
        if (tid < cnt) {
            int srcl = g_srclist[off + base + tid];
            sm_src[tid] = srcl;
            int srcg = g * NN + srcl;
#pragma unroll
            for (int h2 = 0; h2 < 4; h2++) {
                float e = leaky(g_asrc[srcg * 4 + h2] + g_adst[node * 4 + h2]);
                sm_alpha[tid * 4 + h2] = expf(e - sm_m[h2]) / sm_s[h2];
            }
        }
        __syncthreads();
        for (int j = 0; j < cnt; j++) {
            int srcg = g * NN + sm_src[j];
            acc += sm_alpha[j * 4 + hd] * g_hfeat[srcg * 256 + tid];
        }
    }

    sred[tid] = acc;
    __syncthreads();
    if (tid < 64) {
        float v = (sred[tid] + sred[tid + 64] + sred[tid + 128] + sred[tid + 192])
                  * 0.25f + bias[tid];
        if (relu_flag) v = fmaxf(v, 0.f);
        if (which == 0) g_gat1[node * 64 + tid] = v;
        else            g_gat2[node * 64 + tid] = v;
    }
}

// -------------------- GRU layer-0 input matmul, batched over all t ----------
// rows r = t*4000 + b*1000 + n ; reads g_gat2[(b*8+t)*1000+n]
__global__ __launch_bounds__(192)
void gi_kernel(const float* __restrict__ Wih0, const float* __restrict__ bih0) {
    __shared__ float xs[4096];
    int tid = threadIdx.x;
    int rowbase = blockIdx.x * 64;
    for (int i = tid; i < 4096; i += 192) {
        int r = i >> 6, k = i & 63;
        int row = rowbase + r;
        int t = row / BN, bn = row % BN;
        int b = bn / NN, n = bn % NN;
        xs[i] = g_gat2[((b * NT + t) * NN + n) * 64 + k];
    }
    __syncthreads();
    float acc[64];
#pragma unroll
    for (int r = 0; r < 64; r++) acc[r] = 0.f;
    int j = tid;
    for (int k = 0; k < 64; k++) {
        float w = Wih0[j * 64 + k];
#pragma unroll
        for (int r = 0; r < 64; r++) acc[r] += xs[r * 64 + k] * w;
    }
    float bj = bih0[j];
    for (int r = 0; r < 64; r++)
        g_gi[(rowbase + r) * 192 + j] = acc[r] + bj;
}

// -------------------- fused 2-layer GRU step ---------------------------------
__device__ __forceinline__ float sigm(float x) { return 1.f / (1.f + expf(-x)); }

__global__ __launch_bounds__(192)
void gru_step_kernel(const float* __restrict__ Whh0, const float* __restrict__ bhh0,
                     const float* __restrict__ Wih1, const float* __restrict__ bih1,
                     const float* __restrict__ Whh1, const float* __restrict__ bhh1,
                     int t) {
    const int R = 32;
    __shared__ float h1s[R * 64];
    __shared__ float h2s[R * 64];
    __shared__ float st[4 * R * 64];
    int tid = threadIdx.x;
    int rowbase = blockIdx.x * R;

    for (int i = tid; i < R * 64; i += 192) {
        h1s[i] = g_h1[rowbase * 64 + i];
        h2s[i] = g_h2[rowbase * 64 + i];
    }
    __syncthreads();

    int j = tid;
    int gate = j >> 6, c = j & 63;

    // ---- layer 1: gh = h1 @ Whh0^T + bhh0 ; gi precomputed ----
    float acc[R];
#pragma unroll
    for (int r = 0; r < R; r++) acc[r] = 0.f;
    for (int k = 0; k < 64; k++) {
        float w = Whh0[j * 64 + k];
#pragma unroll
        for (int r = 0; r < R; r++) acc[r] += h1s[r * 64 + k] * w;
    }
    float bh = bhh0[j];
    for (int r = 0; r < R; r++) {
        float gi = g_gi[(t * BN + rowbase + r) * 192 + j];
        float gh = acc[r] + bh;
        if (gate == 0)      st[0 * R * 64 + r * 64 + c] = gi + gh;
        else if (gate == 1) st[1 * R * 64 + r * 64 + c] = gi + gh;
        else { st[2 * R * 64 + r * 64 + c] = gi; st[3 * R * 64 + r * 64 + c] = gh; }
    }
    __syncthreads();
    for (int idx = tid; idx < R * 64; idx += 192) {
        float rg = sigm(st[idx]);
        float zg = sigm(st[R * 64 + idx]);
        float nn = tanhf(st[2 * R * 64 + idx] + rg * st[3 * R * 64 + idx]);
        float h1n = (1.f - zg) * nn + zg * h1s[idx];
        h1s[idx] = h1n;
        g_h1[rowbase * 64 + idx] = h1n;
    }
    __syncthreads();

    // ---- layer 2: gi = h1n @ Wih1^T + bih1 ; gh = h2 @ Whh1^T + bhh1 ----
    float acci[R];
#pragma unroll
    for (int r = 0; r < R; r++) { acc[r] = 0.f; acci[r] = 0.f; }
    for (int k = 0; k < 64; k++) {
        float wi = Wih1[j * 64 + k];
        float wh = Whh1[j * 64 + k];
#pragma unroll
        for (int r = 0; r < R; r++) {
            acci[r] += h1s[r * 64 + k] * wi;
            acc[r]  += h2s[r * 64 + k] * wh;
        }
    }
    float bi = bih1[j];
    bh = bhh1[j];
    for (int r = 0; r < R; r++) {
        float gi = acci[r] + bi;
        float gh = acc[r] + bh;
        if (gate == 0)      st[0 * R * 64 + r * 64 + c] = gi + gh;
        else if (gate == 1) st[1 * R * 64 + r * 64 + c] = gi + gh;
        else { st[2 * R * 64 + r * 64 + c] = gi; st[3 * R * 64 + r * 64 + c] = gh; }
    }
    __syncthreads();
    for (int idx = tid; idx < R * 64; idx += 192) {
        float rg = sigm(st[idx]);
        float zg = sigm(st[R * 64 + idx]);
        float nn = tanhf(st[2 * R * 64 + idx] + rg * st[3 * R * 64 + idx]);
        float h2n = (1.f - zg) * nn + zg * h2s[idx];
        g_h2[rowbase * 64 + idx] = h2n;
    }
}

// -------------------- final MLP ----------------------------------------------
__global__ __launch_bounds__(64)
void mlp_kernel(const float* __restrict__ pW1, const float* __restrict__ pb1,
                const float* __restrict__ pW2, const float* __restrict__ pb2,
                float* __restrict__ out) {
    __shared__ float hs[64 * 64];
    __shared__ float mid[64 * 64];
    int tid = threadIdx.x;
    int rowbase = blockIdx.x * 64;
    int rows = min(64, BN - rowbase);
    for (int i = tid; i < 64 * 64; i += 64)
        hs[i] = (i < rows * 64) ? g_h2[rowbase * 64 + i] : 0.f;
    __syncthreads();
    float acc[64];
#pragma unroll
    for (int r = 0; r < 64; r++) acc[r] = 0.f;
    for (int k = 0; k < 64; k++) {
        float w = pW1[k * 64 + tid];
#pragma unroll
        for (int r = 0; r < 64; r++) acc[r] += hs[r * 64 + k] * w;
    }
    float b = pb1[tid];
    for (int r = 0; r < 64; r++)
        mid[r * 64 + tid] = fmaxf(acc[r] + b, 0.f);
    __syncthreads();
    for (int idx = tid; idx < rows * 10; idx += 64) {
        int r = idx / 10, o = idx % 10;
        float a = pb2[o];
        for (int k = 0; k < 64; k++) a += mid[r * 64 + k] * pW2[k * 10 + o];
        out[(rowbase + r) * 10 + o] = a;
    }
}

// -------------------- launch --------------------------------------------------
extern "C" void kernel_launch(void* const* d_in, const int* in_sizes, int n_in,
                              void* d_out, int out_size) {
    const float* x    = (const float*)d_in[0];
    const int*   ei   = (const int*)  d_in[1];
    const float* W1   = (const float*)d_in[3];
    const float* as1  = (const float*)d_in[4];
    const float* ad1  = (const float*)d_in[5];
    const float* b1   = (const float*)d_in[6];
    const float* W2   = (const float*)d_in[7];
    const float* as2  = (const float*)d_in[8];
    const float* ad2  = (const float*)d_in[9];
    const float* b2   = (const float*)d_in[10];
    const float* Wih0 = (const float*)d_in[13];
    const float* Whh0 = (const float*)d_in[14];
    const float* bih0 = (const float*)d_in[15];
    const float* bhh0 = (const float*)d_in[16];
    const float* Wih1 = (const float*)d_in[17];
    const float* Whh1 = (const float*)d_in[18];
    const float* bih1 = (const float*)d_in[19];
    const float* bhh1 = (const float*)d_in[20];
    const float* pW1  = (const float*)d_in[21];
    const float* pb1  = (const float*)d_in[22];
    const float* pW2  = (const float*)d_in[23];
    const float* pb2  = (const float*)d_in[24];
    float* out = (float*)d_out;

    init_kernel<<<256, 256>>>();
    hist_kernel<<<2000, 256>>>(ei);
    scan_kernel<<<1, 1024>>>();
    scatter_kernel<<<2000, 256>>>(ei);

    // GAT layer 1
    prologue_kernel<<<GN / 64, 256>>>(x, W1, 0);
    att_kernel<<<GN, 256>>>(as1, ad1);
    aggregate_kernel<<<GN, 256>>>(b1, 1, 0);

    // GAT layer 2
    prologue_kernel<<<GN / 64, 256>>>(nullptr, W2, 1);
    att_kernel<<<GN, 256>>>(as2, ad2);
    aggregate_kernel<<<GN, 256>>>(b2, 0, 1);

    // GRU
    gi_kernel<<<(NT * BN) / 64, 192>>>(Wih0, bih0);
    for (int t = 0; t < NT; t++)
        gru_step_kernel<<<BN / 32, 192>>>(Whh0, bhh0, Wih1, bih1, Whh1, bhh1, t);

    // head
    mlp_kernel<<<(BN + 63) / 64, 64>>>(pW1, pb1, pW2, pb2, out);
}

// round 3
// speedup vs baseline: 1.8949x; 1.8949x over previous
#include <cuda_runtime.h>
#include <math.h>

#define NB    4
#define NN    1000
#define NT    8
#define NF    64
#define NH    64
#define NHEAD 4
#define NE    16000
#define NG    32
#define GN    32000
#define BN    4000
#define TOTE  512000
#define NEG_SLOPE 0.2f

// -------------------- scratch ------------------------------------------------
__device__ float g_hfeat[GN * 256];
__device__ float g_asrc[GN * 4];
__device__ float g_adst[GN * 4];
__device__ float g_gat1[GN * 64];
__device__ float g_gat2[GN * 64];
__device__ float g_gi[NT * BN * 192];
__device__ float g_h1[BN * 64];
__device__ float g_h2[BN * 64];
__device__ int   g_deg[GN];
__device__ int   g_offs[GN + 1];
__device__ int   g_cursor[GN];
__device__ int   g_srclist[TOTE];
// transposed weights [k][j]
__device__ float g_whh0T[64 * 192];
__device__ float g_wih1T[64 * 192];
__device__ float g_whh1T[64 * 192];
__device__ float g_wih0T[64 * 192];

// -------------------- fast math ----------------------------------------------
__device__ __forceinline__ float leaky(float x) { return fmaxf(x, NEG_SLOPE * x); }
__device__ __forceinline__ float fsig(float x) {
    float e = __expf(-fabsf(x));
    float r = __fdividef(1.f, 1.f + e);
    return x >= 0.f ? r : r * e;
}
__device__ __forceinline__ float ftanh(float x) {
    float e = __expf(-2.f * fabsf(x));
    float t = 1.f - __fdividef(2.f * e, 1.f + e);
    return x >= 0.f ? t : -t;
}

// -------------------- init ----------------------------------------------------
__global__ void init_kernel() {
    int total = GN + BN * 64 * 2;
    for (int i = blockIdx.x * blockDim.x + threadIdx.x; i < total;
         i += gridDim.x * blockDim.x) {
        if (i < GN) g_deg[i] = 0;
        else if (i < GN + BN * 64) g_h1[i - GN] = 0.f;
        else g_h2[i - GN - BN * 64] = 0.f;
    }
}

__global__ void wtrans_kernel(const float* __restrict__ Whh0,
                              const float* __restrict__ Wih1,
                              const float* __restrict__ Whh1,
                              const float* __restrict__ Wih0) {
    int i = blockIdx.x * blockDim.x + threadIdx.x;
    if (i >= 12288) return;
    int j = i / 64, k = i % 64;
    g_whh0T[k * 192 + j] = Whh0[i];
    g_wih1T[k * 192 + j] = Wih1[i];
    g_whh1T[k * 192 + j] = Whh1[i];
    g_wih0T[k * 192 + j] = Wih0[i];
}

// -------------------- CSR build ------------------------------------------------
__global__ void hist_kernel(const int* __restrict__ ei) {
    for (int e = blockIdx.x * blockDim.x + threadIdx.x; e < TOTE;
         e += gridDim.x * blockDim.x) {
        int g = e / NE, el = e % NE;
        int dst = ei[(g * 2 + 1) * NE + el];
        atomicAdd(&g_deg[g * NN + dst], 1);
    }
}

__global__ void scan_kernel() {
    __shared__ int wsum[32];
    int tid = threadIdx.x, lane = tid & 31, wid = tid >> 5;
    int base = tid * 32;
    int local = 0;
    for (int i = 0; i < 32; i++) {
        int idx = base + i;
        if (idx < GN) local += g_deg[idx];
    }
    int s = local;
    for (int d = 1; d < 32; d <<= 1) {
        int v = __shfl_up_sync(0xffffffffu, s, d);
        if (lane >= d) s += v;
    }
    if (lane == 31) wsum[wid] = s;
    __syncthreads();
    if (wid == 0) {
        int v = wsum[lane];
        for (int d = 1; d < 32; d <<= 1) {
            int u = __shfl_up_sync(0xffffffffu, v, d);
            if (lane >= d) v += u;
        }
        wsum[lane] = v;
    }
    __syncthreads();
    int prefix = s - local + (wid > 0 ? wsum[wid - 1] : 0);
    int run = prefix;
    for (int i = 0; i < 32; i++) {
        int idx = base + i;
        if (idx < GN) {
            g_offs[idx] = run;
            g_cursor[idx] = run;
            run += g_deg[idx];
        }
    }
    if (tid == 1023) g_offs[GN] = run;
}

__global__ void scatter_kernel(const int* __restrict__ ei) {
    for (int e = blockIdx.x * blockDim.x + threadIdx.x; e < TOTE;
         e += gridDim.x * blockDim.x) {
        int g = e / NE, el = e % NE;
        int src = ei[(g * 2 + 0) * NE + el];
        int dst = ei[(g * 2 + 1) * NE + el];
        int pos = atomicAdd(&g_cursor[g * NN + dst], 1);
        g_srclist[pos] = src;
    }
}

// -------------------- GAT prologue + attention scalars -------------------------
// Block: 64 nodes x 256 cols. 256 threads; thread = (cq = t%64 -> 4 cols, rq = t/64 -> 16 rows)
// mode 0: read from input x; mode 1: read from g_gat1 (device global, NOT a host arg).
__global__ __launch_bounds__(256)
void prologue_kernel(const float* __restrict__ in, const float* __restrict__ W,
                     const float* __restrict__ att_src, const float* __restrict__ att_dst,
                     int mode) {
    __shared__ float xsT[64 * 68];   // [k][r], padded
    int t = threadIdx.x;
    int cq = t & 63, rq = t >> 6;
    int lane = t & 31;
    int nodebase = blockIdx.x * 64;

    for (int linear = t; linear < 4096; linear += 256) {
        int r = linear >> 6, k = linear & 63;
        int node = nodebase + r;
        float v;
        if (mode == 0) {
            int gg = node / NN, n = node % NN;
            int b = gg >> 3, tt = gg & 7;
            v = in[((b * NN + n) * NT + tt) * NF + k];
        } else {
            v = g_gat1[node * 64 + k];
        }
        xsT[k * 68 + r] = v;
    }
    __syncthreads();

    const float4* Wv = (const float4*)W;
    float4 acc[16];
#pragma unroll
    for (int i = 0; i < 16; i++) acc[i] = make_float4(0.f, 0.f, 0.f, 0.f);

    int rbase = rq * 16;
    for (int k = 0; k < 64; k++) {
        float4 w = __ldg(&Wv[k * 64 + cq]);
        const float* xk = &xsT[k * 68 + rbase];
#pragma unroll
        for (int i = 0; i < 4; i++) {
            float4 xv = *(const float4*)&xk[i * 4];
            acc[i * 4 + 0].x += xv.x * w.x; acc[i * 4 + 0].y += xv.x * w.y;
            acc[i * 4 + 0].z += xv.x * w.z; acc[i * 4 + 0].w += xv.x * w.w;
            acc[i * 4 + 1].x += xv.y * w.x; acc[i * 4 + 1].y += xv.y * w.y;
            acc[i * 4 + 1].z += xv.y * w.z; acc[i * 4 + 1].w += xv.y * w.w;
            acc[i * 4 + 2].x += xv.z * w.x; acc[i * 4 + 2].y += xv.z * w.y;
            acc[i * 4 + 2].z += xv.z * w.z; acc[i * 4 + 2].w += xv.z * w.w;
            acc[i * 4 + 3].x += xv.w * w.x; acc[i * 4 + 3].y += xv.w * w.y;
            acc[i * 4 + 3].z += xv.w * w.z; acc[i * 4 + 3].w += xv.w * w.w;
        }
    }

    float4 as4 = __ldg((const float4*)&att_src[cq * 4]);
    float4 ad4 = __ldg((const float4*)&att_dst[cq * 4]);
    int hd = cq >> 4;

#pragma unroll
    for (int i = 0; i < 16; i++) {
        int node = nodebase + rbase + i;
        float4 a = acc[i];
        *(float4*)&g_hfeat[node * 256 + cq * 4] = a;
        float ps = a.x * as4.x + a.y * as4.y + a.z * as4.z + a.w * as4.w;
        float pd = a.x * ad4.x + a.y * ad4.y + a.z * ad4.z + a.w * ad4.w;
#pragma unroll
        for (int o = 8; o; o >>= 1) {
            ps += __shfl_xor_sync(0xffffffffu, ps, o);
            pd += __shfl_xor_sync(0xffffffffu, pd, o);
        }
        if ((lane & 15) == 0) {
            g_asrc[node * 4 + hd] = ps;
            g_adst[node * 4 + hd] = pd;
        }
    }
}

// -------------------- GAT aggregation ------------------------------------------
// one node per block, 128 threads. softmax without max-shift (logits are small).
__global__ __launch_bounds__(128)
void aggregate_kernel(const float* __restrict__ bias, int relu_flag, int which) {
    __shared__ float4 sm_alpha[128];
    __shared__ int    sm_src[128];
    __shared__ float4 sm_sinv;
    __shared__ float  sred[256];

    int node = blockIdx.x;
    int g = node / NN;
    int gbase = g * NN;
    int tid = threadIdx.x;
    int off = g_offs[node];
    int deg = g_offs[node + 1] - off;

    float4 ad4 = *(const float4*)&g_adst[node * 4];
    float4 asn = *(const float4*)&g_asrc[node * 4];

    if (tid < 32) {
        float4 s;
        s.x = s.y = s.z = s.w = 0.f;
        for (int j = tid; j < deg; j += 32) {
            int src = g_srclist[off + j];
            float4 as = __ldg((const float4*)&g_asrc[(gbase + src) * 4]);
            s.x += __expf(leaky(as.x + ad4.x));
            s.y += __expf(leaky(as.y + ad4.y));
            s.z += __expf(leaky(as.z + ad4.z));
            s.w += __expf(leaky(as.w + ad4.w));
        }
        if (tid == 0) {
            s.x += __expf(leaky(asn.x + ad4.x));
            s.y += __expf(leaky(asn.y + ad4.y));
            s.z += __expf(leaky(asn.z + ad4.z));
            s.w += __expf(leaky(asn.w + ad4.w));
        }
#pragma unroll
        for (int o = 16; o; o >>= 1) {
            s.x += __shfl_xor_sync(0xffffffffu, s.x, o);
            s.y += __shfl_xor_sync(0xffffffffu, s.y, o);
            s.z += __shfl_xor_sync(0xffffffffu, s.z, o);
            s.w += __shfl_xor_sync(0xffffffffu, s.w, o);
        }
        if (tid == 0) {
            float4 inv;
            inv.x = __fdividef(1.f, s.x); inv.y = __fdividef(1.f, s.y);
            inv.z = __fdividef(1.f, s.z); inv.w = __fdividef(1.f, s.w);
            sm_sinv = inv;
        }
    }
    __syncthreads();
    float4 sinv = sm_sinv;

    int head = tid >> 5;
    int pi = tid & 31;
    int cidx = head * 64 + pi * 2;

    float sinv_h = ((const float*)&sinv)[head];
    float ash = ((const float*)&asn)[head];
    float adh = ((const float*)&ad4)[head];
    float a_self = __expf(leaky(ash + adh)) * sinv_h;
    float2 hv = *(const float2*)&g_hfeat[node * 256 + cidx];
    float accx = a_self * hv.x;
    float accy = a_self * hv.y;

    for (int base = 0; base < deg; base += 128) {
        int cnt = min(128, deg - base);
        __syncthreads();
        if (tid < cnt) {
            int src = g_srclist[off + base + tid];
            sm_src[tid] = gbase + src;
            float4 as = __ldg((const float4*)&g_asrc[(gbase + src) * 4]);
            float4 al;
            al.x = __expf(leaky(as.x + ad4.x)) * sinv.x;
            al.y = __expf(leaky(as.y + ad4.y)) * sinv.y;
            al.z = __expf(leaky(as.z + ad4.z)) * sinv.z;
            al.w = __expf(leaky(as.w + ad4.w)) * sinv.w;
            sm_alpha[tid] = al;
        }
        __syncthreads();
        const float* alp = (const float*)sm_alpha;
#pragma unroll 4
        for (int j = 0; j < cnt; j++) {
            int sg = sm_src[j];
            float a = alp[j * 4 + head];
            float2 f = *(const float2*)&g_hfeat[sg * 256 + cidx];
            accx += a * f.x;
            accy += a * f.y;
        }
    }

    sred[tid * 2] = accx;
    sred[tid * 2 + 1] = accy;
    __syncthreads();
    if (tid < 32) {
        float vx = sred[tid * 2] + sred[64 + tid * 2] + sred[128 + tid * 2] + sred[192 + tid * 2];
        float vy = sred[tid * 2 + 1] + sred[64 + tid * 2 + 1] + sred[128 + tid * 2 + 1] + sred[192 + tid * 2 + 1];
        float2 b = *(const float2*)&bias[tid * 2];
        vx = vx * 0.25f + b.x;
        vy = vy * 0.25f + b.y;
        if (relu_flag) { vx = fmaxf(vx, 0.f); vy = fmaxf(vy, 0.f); }
        float2 o = make_float2(vx, vy);
        if (which == 0) *(float2*)&g_gat1[node * 64 + tid * 2] = o;
        else            *(float2*)&g_gat2[node * 64 + tid * 2] = o;
    }
}

// -------------------- GRU input matmul (all t), register tiled ------------------
__global__ __launch_bounds__(192)
void gi_kernel(const float* __restrict__ bih0) {
    __shared__ float xsT[64 * 68];
    int t = threadIdx.x;
    int cq = t % 48, rq = t / 48;
    int rowbase = blockIdx.x * 64;

    for (int linear = t; linear < 4096; linear += 192) {
        int r = linear >> 6, k = linear & 63;
        int row = rowbase + r;
        int tt = row / BN, bn = row % BN;
        int b = bn / NN, n = bn % NN;
        xsT[k * 68 + r] = g_gat2[((b * NT + tt) * NN + n) * 64 + k];
    }
    __syncthreads();

    const float4* Wv = (const float4*)g_wih0T;
    float4 acc[16];
#pragma unroll
    for (int i = 0; i < 16; i++) acc[i] = make_float4(0.f, 0.f, 0.f, 0.f);
    int rbase = rq * 16;
    for (int k = 0; k < 64; k++) {
        float4 w = __ldg(&Wv[k * 48 + cq]);
        const float* xk = &xsT[k * 68 + rbase];
#pragma unroll
        for (int i = 0; i < 4; i++) {
            float4 xv = *(const float4*)&xk[i * 4];
            acc[i * 4 + 0].x += xv.x * w.x; acc[i * 4 + 0].y += xv.x * w.y;
            acc[i * 4 + 0].z += xv.x * w.z; acc[i * 4 + 0].w += xv.x * w.w;
            acc[i * 4 + 1].x += xv.y * w.x; acc[i * 4 + 1].y += xv.y * w.y;
            acc[i * 4 + 1].z += xv.y * w.z; acc[i * 4 + 1].w += xv.y * w.w;
            acc[i * 4 + 2].x += xv.z * w.x; acc[i * 4 + 2].y += xv.z * w.y;
            acc[i * 4 + 2].z += xv.z * w.z; acc[i * 4 + 2].w += xv.z * w.w;
            acc[i * 4 + 3].x += xv.w * w.x; acc[i * 4 + 3].y += xv.w * w.y;
            acc[i * 4 + 3].z += xv.w * w.z; acc[i * 4 + 3].w += xv.w * w.w;
        }
    }
    float4 bj = __ldg((const float4*)&bih0[cq * 4]);
#pragma unroll
    for (int i = 0; i < 16; i++) {
        float4 v = acc[i];
        v.x += bj.x; v.y += bj.y; v.z += bj.z; v.w += bj.w;
        *(float4*)&g_gi[(rowbase + rbase + i) * 192 + cq * 4] = v;
    }
}

// -------------------- fused 2-layer GRU step (register tiled, R=16) -------------
// 192 threads: cq=t%48 (4 cols of 192), rq=t/48 (4 rows each of 16)
__global__ __launch_bounds__(192)
void gru_step_kernel(const float* __restrict__ bhh0,
                     const float* __restrict__ bih1, const float* __restrict__ bhh1,
                     int t) {
    const int R = 16;
    __shared__ float h1T[64 * 20];   // [k][r] padded
    __shared__ float h2T[64 * 20];
    __shared__ float st[R * 196];    // gates r,z,n_gi per row
    __shared__ float st2[R * 64];    // n_gh per row

    int tid = threadIdx.x;
    int cq = tid % 48, rq = tid / 48;
    int rowbase = blockIdx.x * R;
    int cbase = cq * 4;
    int gate = cq >> 4;
    int rb = rq * 4;

    for (int idx = tid; idx < R * 64; idx += 192) {
        int r = idx >> 6, k = idx & 63;
        h1T[k * 20 + r] = g_h1[(rowbase + r) * 64 + k];
        h2T[k * 20 + r] = g_h2[(rowbase + r) * 64 + k];
    }
    __syncthreads();

    const float4* W0 = (const float4*)g_whh0T;
    // ---- layer 1: gh = h1 @ Whh0^T ----
    {
        float4 acc[4];
#pragma unroll
        for (int i = 0; i < 4; i++) acc[i] = make_float4(0.f, 0.f, 0.f, 0.f);
        for (int k = 0; k < 64; k++) {
            float4 w = __ldg(&W0[k * 48 + cq]);
            float4 ra = *(const float4*)&h1T[k * 20 + rb];
            acc[0].x += ra.x * w.x; acc[0].y += ra.x * w.y; acc[0].z += ra.x * w.z; acc[0].w += ra.x * w.w;
            acc[1].x += ra.y * w.x; acc[1].y += ra.y * w.y; acc[1].z += ra.y * w.z; acc[1].w += ra.y * w.w;
            acc[2].x += ra.z * w.x; acc[2].y += ra.z * w.y; acc[2].z += ra.z * w.z; acc[2].w += ra.z * w.w;
            acc[3].x += ra.w * w.x; acc[3].y += ra.w * w.y; acc[3].z += ra.w * w.z; acc[3].w += ra.w * w.w;
        }
        float4 bh = __ldg((const float4*)&bhh0[cbase]);
#pragma unroll
        for (int i = 0; i < 4; i++) {
            int r = rb + i;
            float4 gi = __ldg((const float4*)&g_gi[(t * BN + rowbase + r) * 192 + cbase]);
            float4 gh;
            gh.x = acc[i].x + bh.x; gh.y = acc[i].y + bh.y;
            gh.z = acc[i].z + bh.z; gh.w = acc[i].w + bh.w;
            if (gate < 2) {
                float4 v = make_float4(gi.x + gh.x, gi.y + gh.y, gi.z + gh.z, gi.w + gh.w);
                *(float4*)&st[r * 196 + cbase] = v;
            } else {
                *(float4*)&st[r * 196 + cbase] = gi;
                *(float4*)&st2[r * 64 + (cbase - 128)] = gh;
            }
        }
    }
    __syncthreads();

    // ---- layer 1 nonlinearity ----
    for (int idx = tid; idx < R * 64; idx += 192) {
        int r = idx >> 6, c = idx & 63;
        float rg = fsig(st[r * 196 + c]);
        float zg = fsig(st[r * 196 + 64 + c]);
        float nv = ftanh(st[r * 196 + 128 + c] + rg * st2[r * 64 + c]);
        float h1o = h1T[c * 20 + r];
        float h1n = (1.f - zg) * nv + zg * h1o;
        h1T[c * 20 + r] = h1n;
        g_h1[(rowbase + r) * 64 + c] = h1n;
    }
    __syncthreads();

    const float4* Wi1 = (const float4*)g_wih1T;
    const float4* Wh1 = (const float4*)g_whh1T;
    // ---- layer 2: gi = h1n @ Wih1^T ; gh = h2 @ Whh1^T ----
    {
        float4 acci[4], acch[4];
#pragma unroll
        for (int i = 0; i < 4; i++) {
            acci[i] = make_float4(0.f, 0.f, 0.f, 0.f);
            acch[i] = make_float4(0.f, 0.f, 0.f, 0.f);
        }
        for (int k = 0; k < 64; k++) {
            float4 wi = __ldg(&Wi1[k * 48 + cq]);
            float4 wh = __ldg(&Wh1[k * 48 + cq]);
            float4 a1 = *(const float4*)&h1T[k * 20 + rb];
            float4 a2 = *(const float4*)&h2T[k * 20 + rb];
            acci[0].x += a1.x * wi.x; acci[0].y += a1.x * wi.y; acci[0].z += a1.x * wi.z; acci[0].w += a1.x * wi.w;
            acci[1].x += a1.y * wi.x; acci[1].y += a1.y * wi.y; acci[1].z += a1.y * wi.z; acci[1].w += a1.y * wi.w;
            acci[2].x += a1.z * wi.x; acci[2].y += a1.z * wi.y; acci[2].z += a1.z * wi.z; acci[2].w += a1.z * wi.w;
            acci[3].x += a1.w * wi.x; acci[3].y += a1.w * wi.y; acci[3].z += a1.w * wi.z; acci[3].w += a1.w * wi.w;
            acch[0].x += a2.x * wh.x; acch[0].y += a2.x * wh.y; acch[0].z += a2.x * wh.z; acch[0].w += a2.x * wh.w;
            acch[1].x += a2.y * wh.x; acch[1].y += a2.y * wh.y; acch[1].z += a2.y * wh.z; acch[1].w += a2.y * wh.w;
            acch[2].x += a2.z * wh.x; acch[2].y += a2.z * wh.y; acch[2].z += a2.z * wh.z; acch[2].w += a2.z * wh.w;
            acch[3].x += a2.w * wh.x; acch[3].y += a2.w * wh.y; acch[3].z += a2.w * wh.z; acch[3].w += a2.w * wh.w;
        }
        float4 bi = __ldg((const float4*)&bih1[cbase]);
        float4 bh = __ldg((const float4*)&bhh1[cbase]);
#pragma unroll
        for (int i = 0; i < 4; i++) {
            int r = rb + i;
            float4 gi, gh;
            gi.x = acci[i].x + bi.x; gi.y = acci[i].y + bi.y;
            gi.z = acci[i].z + bi.z; gi.w = acci[i].w + bi.w;
            gh.x = acch[i].x + bh.x; gh.y = acch[i].y + bh.y;
            gh.z = acch[i].z + bh.z; gh.w = acch[i].w + bh.w;
            if (gate < 2) {
                float4 v = make_float4(gi.x + gh.x, gi.y + gh.y, gi.z + gh.z, gi.w + gh.w);
                *(float4*)&st[r * 196 + cbase] = v;
            } else {
                *(float4*)&st[r * 196 + cbase] = gi;
                *(float4*)&st2[r * 64 + (cbase - 128)] = gh;
            }
        }
    }
    __syncthreads();

    for (int idx = tid; idx < R * 64; idx += 192) {
        int r = idx >> 6, c = idx & 63;
        float rg = fsig(st[r * 196 + c]);
        float zg = fsig(st[r * 196 + 64 + c]);
        float nv = ftanh(st[r * 196 + 128 + c] + rg * st2[r * 64 + c]);
        float h2o = h2T[c * 20 + r];
        float h2n = (1.f - zg) * nv + zg * h2o;
        g_h2[(rowbase + r) * 64 + c] = h2n;
    }
}

// -------------------- final MLP --------------------------------------------------
__global__ __launch_bounds__(64)
void mlp_kernel(const float* __restrict__ pW1, const float* __restrict__ pb1,
                const float* __restrict__ pW2, const float* __restrict__ pb2,
                float* __restrict__ out) {
    __shared__ float hs[64 * 64];
    __shared__ float mid[64 * 64];
    int tid = threadIdx.x;
    int rowbase = blockIdx.x * 64;
    int rows = min(64, BN - rowbase);
    for (int i = tid; i < 64 * 64; i += 64)
        hs[i] = (i < rows * 64) ? g_h2[rowbase * 64 + i] : 0.f;
    __syncthreads();
    float acc[64];
#pragma unroll
    for (int r = 0; r < 64; r++) acc[r] = 0.f;
    for (int k = 0; k < 64; k++) {
        float w = pW1[k * 64 + tid];
#pragma unroll
        for (int r = 0; r < 64; r++) acc[r] += hs[r * 64 + k] * w;
    }
    float b = pb1[tid];
    for (int r = 0; r < 64; r++)
        mid[r * 64 + tid] = fmaxf(acc[r] + b, 0.f);
    __syncthreads();
    for (int idx = tid; idx < rows * 10; idx += 64) {
        int r = idx / 10, o = idx % 10;
        float a = pb2[o];
        for (int k = 0; k < 64; k++) a += mid[r * 64 + k] * pW2[k * 10 + o];
        out[(rowbase + r) * 10 + o] = a;
    }
}

// -------------------- launch ------------------------------------------------------
extern "C" void kernel_launch(void* const* d_in, const int* in_sizes, int n_in,
                              void* d_out, int out_size) {
    const float* x    = (const float*)d_in[0];
    const int*   ei   = (const int*)  d_in[1];
    const float* W1   = (const float*)d_in[3];
    const float* as1  = (const float*)d_in[4];
    const float* ad1  = (const float*)d_in[5];
    const float* b1   = (const float*)d_in[6];
    const float* W2   = (const float*)d_in[7];
    const float* as2  = (const float*)d_in[8];
    const float* ad2  = (const float*)d_in[9];
    const float* b2   = (const float*)d_in[10];
    const float* Wih0 = (const float*)d_in[13];
    const float* Whh0 = (const float*)d_in[14];
    const float* bih0 = (const float*)d_in[15];
    const float* bhh0 = (const float*)d_in[16];
    const float* Wih1 = (const float*)d_in[17];
    const float* Whh1 = (const float*)d_in[18];
    const float* bih1 = (const float*)d_in[19];
    const float* bhh1 = (const float*)d_in[20];
    const float* pW1  = (const float*)d_in[21];
    const float* pb1  = (const float*)d_in[22];
    const float* pW2  = (const float*)d_in[23];
    const float* pb2  = (const float*)d_in[24];
    float* out = (float*)d_out;

    init_kernel<<<256, 256>>>();
    wtrans_kernel<<<48, 256>>>(Whh0, Wih1, Whh1, Wih0);
    hist_kernel<<<2000, 256>>>(ei);
    scan_kernel<<<1, 1024>>>();
    scatter_kernel<<<2000, 256>>>(ei);

    // GAT layer 1
    prologue_kernel<<<GN / 64, 256>>>(x, W1, as1, ad1, 0);
    aggregate_kernel<<<GN, 128>>>(b1, 1, 0);

    // GAT layer 2
    prologue_kernel<<<GN / 64, 256>>>(nullptr, W2, as2, ad2, 1);
    aggregate_kernel<<<GN, 128>>>(b2, 0, 1);

    // GRU
    gi_kernel<<<(NT * BN) / 64, 192>>>(bih0);
    for (int t = 0; t < NT; t++)
        gru_step_kernel<<<BN / 16, 192>>>(bhh0, bih1, bhh1, t);

    // head
    mlp_kernel<<<(BN + 63) / 64, 64>>>(pW1, pb1, pW2, pb2, out);
}